// round 3
// baseline (speedup 1.0000x reference)
#include <cuda_runtime.h>

// Problem constants (from reference setup_inputs)
#define T_DIM 16
#define B_DIM 32
#define N_DIM 196
#define C_DIM 512
#define TB_STRIDE (B_DIM * N_DIM * C_DIM)   // elements per timestep
#define SPIKES_ELEMS ((size_t)T_DIM * B_DIM * N_DIM * C_DIM)
#define NUM_UNITS 256                        // (b, ctile) work units
#define GRID_X 148                           // one block per SM

// 148 blocks (every SM busy from cycle 0). Units 0..255; block bid runs unit
// bid, then unit bid+148 if it exists (108 blocks run 2 units, 40 run 1).
// Block = 32 c-lanes (float2 -> 64 c) x 32 n-groups; each thread carries 7
// v-states covering all N=196. Per timestep: compute+store, then batch the
// next timestep's 7 LDG.64 (crossing the unit boundary at t=15 so the
// pipeline never drains), then publish partials, one barrier, 64-thread
// vpool reduction hidden under the in-flight loads.
__global__ __launch_bounds__(1024, 1)
void lif_dual_kernel(const float* __restrict__ x,
                     const float* __restrict__ decay,
                     float* __restrict__ spikes,
                     float* __restrict__ vpool) {
    const int cx   = threadIdx.x;        // 0..31
    const int ny   = threadIdx.y;        // 0..31
    const int flat = ny * 32 + cx;
    const int bid  = blockIdx.x;

    const float d = decay[0];
    const float inv_n = 1.0f / (float)N_DIM;
    const bool last_ok = (ny < (N_DIM - 6 * 32));   // ny < 4

    __shared__ float red[2][32][64];

    const int nu = (bid + GRID_X < NUM_UNITS) ? 2 : 1;

    // base(unit) = ((b*N + ny)*C + ctile*64 + cx*2), b = unit>>3, ctile = unit&7
    auto unit_base = [&](int unit) -> size_t {
        return ((size_t)(unit >> 3) * N_DIM + ny) * C_DIM + (unit & 7) * 64 + cx * 2;
    };

    // Prime the pipeline for the first unit.
    float2 xv[7];
    {
        const size_t b0 = unit_base(bid);
#pragma unroll
        for (int k = 0; k < 6; k++)
            xv[k] = __ldcs(reinterpret_cast<const float2*>(x + b0 + (size_t)k * 32 * C_DIM));
        if (last_ok)
            xv[6] = __ldcs(reinterpret_cast<const float2*>(x + b0 + (size_t)6 * 32 * C_DIM));
    }

#pragma unroll 1
    for (int u = 0; u < nu; u++) {
        const int unit  = bid + u * GRID_X;
        const int ctile = unit & 7;
        const int b     = unit >> 3;
        const size_t base = unit_base(unit);

        float2 v[7];
#pragma unroll
        for (int k = 0; k < 7; k++) v[k] = make_float2(0.0f, 0.0f);

#pragma unroll 1
        for (int t = 0; t < T_DIM; t++) {
            const size_t off = base + (size_t)t * TB_STRIDE;
            const int par = t & 1;

            float2 p = make_float2(0.0f, 0.0f);
#pragma unroll
            for (int k = 0; k < 7; k++) {
                if (k == 6 && !last_ok) break;
                float2 vv = v[k];
                vv.x = fmaf(d, vv.x, xv[k].x);
                vv.y = fmaf(d, vv.y, xv[k].y);
                p.x += vv.x;                        // vpool uses PRE-reset v
                p.y += vv.y;
                float sx = (vv.x >= 1.0f) ? 1.0f : 0.0f;
                float sy = (vv.y >= 1.0f) ? 1.0f : 0.0f;
                __stcs(reinterpret_cast<float2*>(spikes + off + (size_t)k * 32 * C_DIM),
                       make_float2(sx, sy));
                vv.x = (sx != 0.0f) ? 0.0f : vv.x;  // hard reset
                vv.y = (sy != 0.0f) ? 0.0f : vv.y;
                v[k] = vv;
            }

            // Prefetch the next timestep (or the next unit's t=0) BEFORE the
            // barrier so the reduction below is hidden by memory latency and
            // the pipeline never drains across the unit switch.
            const bool more = (t < T_DIM - 1) || (u + 1 < nu);
            if (more) {
                const size_t noff = (t < T_DIM - 1) ? (off + (size_t)TB_STRIDE)
                                                    : unit_base(bid + GRID_X);
#pragma unroll
                for (int k = 0; k < 6; k++)
                    xv[k] = __ldcs(reinterpret_cast<const float2*>(x + noff + (size_t)k * 32 * C_DIM));
                if (last_ok)
                    xv[6] = __ldcs(reinterpret_cast<const float2*>(x + noff + (size_t)6 * 32 * C_DIM));
            }

            // Publish partial sums for this timestep.
            *reinterpret_cast<float2*>(&red[par][ny][2 * cx]) = p;

            __syncthreads();

            // 64 threads reduce the 32 n-group partials for 64 c columns.
            // One barrier is safe: the next iteration writes the other parity
            // buffer, and rewriting this one requires passing the next barrier.
            if (flat < 64) {
                float s = 0.0f;
#pragma unroll
                for (int j = 0; j < 32; j++) s += red[par][j][flat];
                vpool[((size_t)t * B_DIM + b) * C_DIM + ctile * 64 + flat] = s * inv_n;
            }
        }
        __syncthreads();   // unit boundary: red[] parity reuse + v reinit
    }
}

extern "C" void kernel_launch(void* const* d_in, const int* in_sizes, int n_in,
                              void* d_out, int out_size) {
    const float* x     = (const float*)d_in[0];
    const float* decay = (const float*)d_in[1];
    float* spikes = (float*)d_out;
    float* vpool  = (float*)d_out + SPIKES_ELEMS;

    dim3 grid(GRID_X, 1);   // every SM gets a block from cycle 0
    dim3 block(32, 32);     // 1024 threads
    lif_dual_kernel<<<grid, block>>>(x, decay, spikes, vpool);
}